// round 12
// baseline (speedup 1.0000x reference)
#include <cuda_runtime.h>
#include <cuda_bf16.h>
#include <cstdint>

// Problem constants
#define T_DIM 512
#define B_DIM 128
#define I_DIM 512
#define H_DIM 1024
#define BH (B_DIM * H_DIM)

// ---------------- scratch (static device globals: allocation-free) ----------
__device__ float g_pre[T_DIM * B_DIM * H_DIM];            // 268 MB, reused
__device__ float g_sx1[(T_DIM - 1) * B_DIM * I_DIM];      // layer-1 scaled input
__device__ unsigned g_bar4[4 * 64];                       // per-rowgroup barrier counters
// h state as pre-split bf16, double-buffered across steps
__device__ __nv_bfloat16 g_hhi[2 * BH], g_hlo[2 * BH];
// transposed + bf16-split weights: [N][K] row-major, K contiguous
__device__ __nv_bfloat16 g_w0t_hi[H_DIM * I_DIM], g_w0t_lo[H_DIM * I_DIM];
__device__ __nv_bfloat16 g_wi1t_hi[H_DIM * H_DIM], g_wi1t_lo[H_DIM * H_DIM];
__device__ __nv_bfloat16 g_ws1t_hi[H_DIM * I_DIM], g_ws1t_lo[H_DIM * I_DIM];

// ---------------- cp.async helpers -----------------------------------------
__device__ __forceinline__ void cp_async16(void* sdst, const void* gsrc) {
    unsigned s = (unsigned)__cvta_generic_to_shared(sdst);
    asm volatile("cp.async.cg.shared.global [%0], [%1], 16;" :: "r"(s), "l"(gsrc));
}
__device__ __forceinline__ void cp_commit() {
    asm volatile("cp.async.commit_group;" ::: "memory");
}
template <int N>
__device__ __forceinline__ void cp_wait() {
    asm volatile("cp.async.wait_group %0;" :: "n"(N) : "memory");
}

__device__ __forceinline__ void mma_bf16(float* c, const uint32_t* a, const uint32_t* b) {
    asm volatile(
        "mma.sync.aligned.m16n8k16.row.col.f32.bf16.bf16.f32 "
        "{%0,%1,%2,%3}, {%4,%5,%6,%7}, {%8,%9}, {%0,%1,%2,%3};"
        : "+f"(c[0]), "+f"(c[1]), "+f"(c[2]), "+f"(c[3])
        : "r"(a[0]), "r"(a[1]), "r"(a[2]), "r"(a[3]), "r"(b[0]), "r"(b[1]));
}

// ---------------- small elementwise kernels --------------------------------
__global__ void k_sx1(const float* __restrict__ x, float* __restrict__ o,
                      int n, int off) {
    int i = blockIdx.x * 256 + threadIdx.x;
    if (i < n) o[i] = 0.5f * (x[i] + x[i + off]);
}
__global__ void k_reset_bar() {
    if (threadIdx.x < 4 * 64) g_bar4[threadIdx.x] = 0u;
}

// transpose + bf16 hi/lo split: W[K,N] (+optional W2) -> Thi/Tlo [N,K]
__global__ void k_tsplit(const float* __restrict__ W, const float* __restrict__ W2,
                         __nv_bfloat16* __restrict__ Thi, __nv_bfloat16* __restrict__ Tlo,
                         int K, int N) {
    __shared__ float s[32][33];
    int k0 = blockIdx.x * 32, n0 = blockIdx.y * 32;
    int tx = threadIdx.x, ty = threadIdx.y;   // 32 x 8
#pragma unroll
    for (int i = 0; i < 4; i++) {
        int k = k0 + ty + i * 8;
        float v = W[(size_t)k * N + n0 + tx];
        if (W2) v += W2[(size_t)k * N + n0 + tx];
        s[ty + i * 8][tx] = v;
    }
    __syncthreads();
#pragma unroll
    for (int i = 0; i < 4; i++) {
        int n = n0 + ty + i * 8;
        float v = s[tx][ty + i * 8];
        __nv_bfloat16 h = __float2bfloat16(v);
        Thi[(size_t)n * K + k0 + tx] = h;
        Tlo[(size_t)n * K + k0 + tx] = __float2bfloat16(v - __bfloat162float(h));
    }
}

// ---------------- HMMA split-bf16 GEMM: 512 threads (proven R10) ------------
#define PITCH 40
#define TILE_HL (128 * PITCH)
#define SM_A 0
#define SM_B (4 * TILE_HL)
#define SM_TOTAL_BF16 (8 * TILE_HL)

__global__ __launch_bounds__(512) void tc_gemm(
    float* __restrict__ C,
    const float* __restrict__ A0, int K0,
    const __nv_bfloat16* __restrict__ B0hi, const __nv_bfloat16* __restrict__ B0lo,
    const float* __restrict__ A1, int K1,
    const __nv_bfloat16* __restrict__ B1hi, const __nv_bfloat16* __restrict__ B1lo)
{
    extern __shared__ __align__(16) __nv_bfloat16 sm[];
    const int tid = threadIdx.x;
    const int wid = tid >> 5, lane = tid & 31;
    const int g = lane >> 2, tg = lane & 3;
    const int wm = (wid >> 2) * 32, wn = (wid & 3) * 32;
    const int mrow0 = blockIdx.y * 128;
    const int ncol0 = blockIdx.x * 128;

    const int NI0 = K0 / 32;
    const int NI = NI0 + K1 / 32;

    float acc[2][4][4];
#pragma unroll
    for (int i = 0; i < 2; i++)
#pragma unroll
        for (int j = 0; j < 4; j++)
#pragma unroll
            for (int q = 0; q < 4; q++) acc[i][j][q] = 0.f;

    const int ar = tid >> 2, ah = (tid & 3) * 8;
    const int bhl = tid >> 8, br = (tid & 255) >> 1, bseg = (tid & 1) * 16;

#define A_SRC(A, K, koff) ((const float4*)((A) + (size_t)(mrow0 + ar) * (K) + (koff) + ah))
#define STS_A(buf, st)                                                                 \
    {                                                                                  \
        __nv_bfloat16* dh = sm + SM_A + ((buf) * 2 + 0) * TILE_HL + ar * PITCH + ah;   \
        __nv_bfloat16* dl = sm + SM_A + ((buf) * 2 + 1) * TILE_HL + ar * PITCH + ah;   \
        float f[8] = {st[0].x, st[0].y, st[0].z, st[0].w,                              \
                      st[1].x, st[1].y, st[1].z, st[1].w};                             \
        uint32_t hi2[4], lo2[4];                                                       \
        _Pragma("unroll")                                                              \
        for (int j = 0; j < 4; j++) {                                                  \
            __nv_bfloat16 h0 = __float2bfloat16(f[2 * j]);                             \
            __nv_bfloat16 h1 = __float2bfloat16(f[2 * j + 1]);                         \
            __nv_bfloat16 l0 = __float2bfloat16(f[2 * j] - __bfloat162float(h0));      \
            __nv_bfloat16 l1 = __float2bfloat16(f[2 * j + 1] - __bfloat162float(h1));  \
            hi2[j] = (uint32_t)__bfloat16_as_ushort(h0) |                              \
                     ((uint32_t)__bfloat16_as_ushort(h1) << 16);                       \
            lo2[j] = (uint32_t)__bfloat16_as_ushort(l0) |                              \
                     ((uint32_t)__bfloat16_as_ushort(l1) << 16);                       \
        }                                                                              \
        *(uint4*)dh = make_uint4(hi2[0], hi2[1], hi2[2], hi2[3]);                      \
        *(uint4*)dl = make_uint4(lo2[0], lo2[1], lo2[2], lo2[3]);                      \
    }
#define LOAD_B(buf, Bhi, Blo, K, koff)                                                 \
    {                                                                                  \
        const __nv_bfloat16* src = ((bhl) ? (Blo) : (Bhi)) +                           \
                                   (size_t)(ncol0 + br) * (K) + (koff) + bseg;         \
        __nv_bfloat16* dst = sm + SM_B + ((buf) * 2 + bhl) * TILE_HL + br * PITCH +    \
                             bseg;                                                     \
        cp_async16(dst, src);                                                          \
        cp_async16(dst + 8, src + 8);                                                  \
    }

    {
        float4 st[2];
        const float4* s4 = A_SRC(A0, K0, 0);
        st[0] = s4[0]; st[1] = s4[1];
        STS_A(0, st);
        LOAD_B(0, B0hi, B0lo, K0, 0);
        cp_commit();
    }

    for (int i = 0; i < NI; i++) {
        cp_wait<0>();
        __syncthreads();

        const int buf = i & 1;
        float4 st[2];
        bool have_next = (i + 1 < NI);
        if (have_next) {
            int ni = i + 1;
            if (ni < NI0) {
                const float4* s4 = A_SRC(A0, K0, ni * 32);
                st[0] = s4[0]; st[1] = s4[1];
                LOAD_B(buf ^ 1, B0hi, B0lo, K0, ni * 32);
            } else {
                int koff = (ni - NI0) * 32;
                const float4* s4 = A_SRC(A1, K1, koff);
                st[0] = s4[0]; st[1] = s4[1];
                LOAD_B(buf ^ 1, B1hi, B1lo, K1, koff);
            }
            cp_commit();
        }

        const __nv_bfloat16* sAh = sm + SM_A + (buf * 2 + 0) * TILE_HL;
        const __nv_bfloat16* sAl = sm + SM_A + (buf * 2 + 1) * TILE_HL;
        const __nv_bfloat16* sBh = sm + SM_B + (buf * 2 + 0) * TILE_HL;
        const __nv_bfloat16* sBl = sm + SM_B + (buf * 2 + 1) * TILE_HL;
#pragma unroll
        for (int kk = 0; kk < 32; kk += 16) {
            uint32_t bh[4][2], bl[4][2];
#pragma unroll
            for (int nt = 0; nt < 4; nt++) {
                int n = wn + nt * 8 + g;
                bh[nt][0] = *(const uint32_t*)(sBh + n * PITCH + kk + tg * 2);
                bh[nt][1] = *(const uint32_t*)(sBh + n * PITCH + kk + tg * 2 + 8);
                bl[nt][0] = *(const uint32_t*)(sBl + n * PITCH + kk + tg * 2);
                bl[nt][1] = *(const uint32_t*)(sBl + n * PITCH + kk + tg * 2 + 8);
            }
#pragma unroll
            for (int mt = 0; mt < 2; mt++) {
                int r = wm + mt * 16 + g;
                uint32_t a_hi[4], a_lo[4];
                a_hi[0] = *(const uint32_t*)(sAh + r * PITCH + kk + tg * 2);
                a_hi[1] = *(const uint32_t*)(sAh + (r + 8) * PITCH + kk + tg * 2);
                a_hi[2] = *(const uint32_t*)(sAh + r * PITCH + kk + tg * 2 + 8);
                a_hi[3] = *(const uint32_t*)(sAh + (r + 8) * PITCH + kk + tg * 2 + 8);
                a_lo[0] = *(const uint32_t*)(sAl + r * PITCH + kk + tg * 2);
                a_lo[1] = *(const uint32_t*)(sAl + (r + 8) * PITCH + kk + tg * 2);
                a_lo[2] = *(const uint32_t*)(sAl + r * PITCH + kk + tg * 2 + 8);
                a_lo[3] = *(const uint32_t*)(sAl + (r + 8) * PITCH + kk + tg * 2 + 8);
#pragma unroll
                for (int nt = 0; nt < 4; nt++) {
                    mma_bf16(acc[mt][nt], a_hi, bh[nt]);
                    mma_bf16(acc[mt][nt], a_lo, bh[nt]);
                    mma_bf16(acc[mt][nt], a_hi, bl[nt]);
                }
            }
        }

        if (have_next) STS_A(buf ^ 1, st);
    }

#pragma unroll
    for (int mt = 0; mt < 2; mt++) {
#pragma unroll
        for (int nt = 0; nt < 4; nt++) {
            int r0 = mrow0 + wm + mt * 16 + g;
            int c0 = ncol0 + wn + nt * 8 + tg * 2;
            *(float2*)(C + (size_t)r0 * 1024 + c0) =
                make_float2(acc[mt][nt][0], acc[mt][nt][1]);
            *(float2*)(C + (size_t)(r0 + 8) * 1024 + c0) =
                make_float2(acc[mt][nt][2], acc[mt][nt][3]);
        }
    }
#undef A_SRC
#undef STS_A
#undef LOAD_B
}

// ---------------- HMMA persistent recurrence v5: 512 thr, 16-way K-split ----
// Same proven chunk skeleton & coalescing as R8; 4 warps/SMSP for latency
// hiding; pre in registers (frees SMEM for 16 reduce buffers).
#define R5_WP 1032
#define R5_SW (32 * R5_WP)
#define R5_HP 264
#define R5_HB (32 * R5_HP)              // 8448 elems
#define R5_HOFF (2 * R5_SW)             // 66048 elems
#define R5_RED_BYTE (R5_HOFF * 2)       // 132096 (red aliases ring)
#define R5_RPITCH 34
#define R5_RW (32 * R5_RPITCH)          // 1088 floats / warp
#define R5_BYTES (R5_RED_BYTE + 16 * R5_RW * 4 + 256)   // 201984

__global__ __launch_bounds__(512, 1) void recur5(
    const float* __restrict__ pre, float* __restrict__ out,
    const float* __restrict__ Wh,
    __nv_bfloat16* __restrict__ hhi, __nv_bfloat16* __restrict__ hlo,
    int steps)
{
    extern __shared__ __align__(16) __nv_bfloat16 sm2[];
    float* red = (float*)((char*)sm2 + R5_RED_BYTE);
    const int tid = threadIdx.x, wid = tid >> 5, lane = tid & 31;
    const int g = lane >> 2, tg = lane & 3;
    const int rg = blockIdx.x >> 5;
    const int r0 = rg * 32;
    const int c0 = (blockIdx.x & 31) * 32;
    const int erow = tid >> 4, ecol = (tid & 15) * 2;   // epilogue mapping

    // ---- load + split Wh strip into SMEM once ----
    for (int k = wid; k < H_DIM; k += 16) {
        float w = Wh[(size_t)k * H_DIM + c0 + lane];
        __nv_bfloat16 h = __float2bfloat16(w);
        sm2[lane * R5_WP + k] = h;
        sm2[R5_SW + lane * R5_WP + k] = __float2bfloat16(w - __bfloat162float(h));
    }
    __syncthreads();

    unsigned target = 0;
    volatile unsigned* vb = &g_bar4[rg * 64];

    // same global access pattern as proven R8 ISSUE_H, spread over 512 threads
#define ISSUE_H(c, buf, hp)                                                              \
    {                                                                                    \
        _Pragma("unroll")                                                                \
        for (int i = 0; i < 4; i++) {                                                    \
            int f = i * 512 + tid;                                                       \
            int hl = f >> 10, rem = f & 1023;                                            \
            int row = rem >> 5, seg = rem & 31;                                          \
            const __nv_bfloat16* src = (hl ? hlo : hhi) + (size_t)(hp)*BH +              \
                                       (size_t)(r0 + row) * H_DIM + (c)*256 + seg * 8;   \
            cp_async16(sm2 + R5_HOFF + ((buf)*2 + hl) * R5_HB + row * R5_HP + seg * 8,   \
                       src);                                                             \
        }                                                                                \
        cp_commit();                                                                     \
    }

    for (int t = 0; t < steps; t++) {
        // pre -> registers (latency hidden behind chunk loop)
        const float2 pv = __ldcg((const float2*)(
            pre + (size_t)t * BH + (size_t)(r0 + erow) * H_DIM + c0 + ecol));

        float acc[2][4][4];
#pragma unroll
        for (int mt = 0; mt < 2; mt++)
#pragma unroll
            for (int nt = 0; nt < 4; nt++)
#pragma unroll
                for (int q = 0; q < 4; q++) acc[mt][nt][q] = 0.f;

        if (t > 0) {
            const int hp = (t - 1) & 1;
            ISSUE_H(0, 0, hp);
            ISSUE_H(1, 1, hp);
#pragma unroll 1
            for (int c = 0; c < 4; c++) {
                if (c < 3) cp_wait<1>(); else cp_wait<0>();
                __syncthreads();
                const int buf = c & 1;
                const __nv_bfloat16* sAh = sm2 + R5_HOFF + buf * 2 * R5_HB;
                const __nv_bfloat16* sAl = sAh + R5_HB;
                const int kk = wid * 16;           // warp's 16-k slice in chunk
                const int kgl = c * 256 + kk;
                uint32_t ahf[2][4], alf[2][4];
#pragma unroll
                for (int mt = 0; mt < 2; mt++) {
                    const int ra = (mt * 16 + g) * R5_HP + kk + tg * 2;
                    const int rb = (mt * 16 + g + 8) * R5_HP + kk + tg * 2;
                    ahf[mt][0] = *(const uint32_t*)(sAh + ra);
                    ahf[mt][1] = *(const uint32_t*)(sAh + rb);
                    ahf[mt][2] = *(const uint32_t*)(sAh + ra + 8);
                    ahf[mt][3] = *(const uint32_t*)(sAh + rb + 8);
                    alf[mt][0] = *(const uint32_t*)(sAl + ra);
                    alf[mt][1] = *(const uint32_t*)(sAl + rb);
                    alf[mt][2] = *(const uint32_t*)(sAl + ra + 8);
                    alf[mt][3] = *(const uint32_t*)(sAl + rb + 8);
                }
#pragma unroll
                for (int nt = 0; nt < 4; nt++) {
                    const int nb = (nt * 8 + g) * R5_WP + kgl + tg * 2;
                    uint32_t bh[2], bl[2];
                    bh[0] = *(const uint32_t*)(sm2 + nb);
                    bh[1] = *(const uint32_t*)(sm2 + nb + 8);
                    bl[0] = *(const uint32_t*)(sm2 + R5_SW + nb);
                    bl[1] = *(const uint32_t*)(sm2 + R5_SW + nb + 8);
#pragma unroll
                    for (int mt = 0; mt < 2; mt++) {
                        mma_bf16(acc[mt][nt], ahf[mt], bh);
                        mma_bf16(acc[mt][nt], alf[mt], bh);
                        mma_bf16(acc[mt][nt], ahf[mt], bl);
                    }
                }
                __syncthreads();
                if (c < 2) ISSUE_H(c + 2, c & 1, hp);
            }
            // ---- write partials (pitch 34: even -> float2-aligned) ----
            float* rw = red + wid * R5_RW;
#pragma unroll
            for (int mt = 0; mt < 2; mt++)
#pragma unroll
                for (int nt = 0; nt < 4; nt++) {
                    int row = mt * 16 + g, col = nt * 8 + tg * 2;
                    *(float2*)(rw + row * R5_RPITCH + col) =
                        make_float2(acc[mt][nt][0], acc[mt][nt][1]);
                    *(float2*)(rw + (row + 8) * R5_RPITCH + col) =
                        make_float2(acc[mt][nt][2], acc[mt][nt][3]);
                }
            __syncthreads();
        }

        // ---- reduce (16 partials) + epilogue: 2 outputs per thread ----
        {
            float s0 = 0.f, s1 = 0.f;
            if (t > 0) {
#pragma unroll
                for (int w = 0; w < 16; w++) {
                    const float* rp = red + w * R5_RW + erow * R5_RPITCH + ecol;
                    s0 += rp[0]; s1 += rp[1];
                }
            }
            float v0 = tanhf(pv.x + s0), v1 = tanhf(pv.y + s1);
            const size_t gidx = (size_t)(r0 + erow) * H_DIM + c0 + ecol;
            *(float2*)(out + (size_t)t * BH + gidx) = make_float2(v0, v1);

            __nv_bfloat16 h0 = __float2bfloat16(v0), h1 = __float2bfloat16(v1);
            __nv_bfloat16 l0 = __float2bfloat16(v0 - __bfloat162float(h0));
            __nv_bfloat16 l1 = __float2bfloat16(v1 - __bfloat162float(h1));
            const size_t hidx = (size_t)(t & 1) * BH + gidx;
            *(uint32_t*)(hhi + hidx) =
                (uint32_t)__bfloat16_as_ushort(h0) | ((uint32_t)__bfloat16_as_ushort(h1) << 16);
            *(uint32_t*)(hlo + hidx) =
                (uint32_t)__bfloat16_as_ushort(l0) | ((uint32_t)__bfloat16_as_ushort(l1) << 16);
        }

        if (t + 1 < steps) {
            __threadfence();
            __syncthreads();
            target += 32;
            if (tid == 0) {
                atomicAdd((unsigned*)vb, 1u);
                while (*vb < target) __nanosleep(32);
            }
            __syncthreads();
        }
    }
#undef ISSUE_H
}

// ---------------- launch ----------------------------------------------------
extern "C" void kernel_launch(void* const* d_in, const int* in_sizes, int n_in,
                              void* d_out, int out_size)
{
    (void)in_sizes; (void)n_in; (void)out_size;
    const float* x   = (const float*)d_in[0];
    const float* Wi0 = (const float*)d_in[1];
    const float* Wh0 = (const float*)d_in[2];
    const float* Ws0 = (const float*)d_in[3];
    const float* Wi1 = (const float*)d_in[4];
    const float* Wh1 = (const float*)d_in[5];
    const float* Ws1 = (const float*)d_in[6];
    float* out = (float*)d_out;

    void* p;
    cudaGetSymbolAddress(&p, g_pre);     float* pre = (float*)p;
    cudaGetSymbolAddress(&p, g_sx1);     float* sx1 = (float*)p;
    cudaGetSymbolAddress(&p, g_hhi);     __nv_bfloat16* hhi = (__nv_bfloat16*)p;
    cudaGetSymbolAddress(&p, g_hlo);     __nv_bfloat16* hlo = (__nv_bfloat16*)p;
    cudaGetSymbolAddress(&p, g_w0t_hi);  __nv_bfloat16* w0hi = (__nv_bfloat16*)p;
    cudaGetSymbolAddress(&p, g_w0t_lo);  __nv_bfloat16* w0lo = (__nv_bfloat16*)p;
    cudaGetSymbolAddress(&p, g_wi1t_hi); __nv_bfloat16* wi1hi = (__nv_bfloat16*)p;
    cudaGetSymbolAddress(&p, g_wi1t_lo); __nv_bfloat16* wi1lo = (__nv_bfloat16*)p;
    cudaGetSymbolAddress(&p, g_ws1t_hi); __nv_bfloat16* ws1hi = (__nv_bfloat16*)p;
    cudaGetSymbolAddress(&p, g_ws1t_lo); __nv_bfloat16* ws1lo = (__nv_bfloat16*)p;

    cudaFuncSetAttribute(recur5,
                         cudaFuncAttributeMaxDynamicSharedMemorySize, R5_BYTES);
    cudaFuncSetAttribute(tc_gemm,
                         cudaFuncAttributeMaxDynamicSharedMemorySize,
                         SM_TOTAL_BF16 * 2);

    // weight prep: transpose + bf16 hi/lo split
    dim3 tb(32, 8);
    k_tsplit<<<dim3(I_DIM / 32, H_DIM / 32), tb>>>(Wi0, Ws0, w0hi, w0lo, I_DIM, H_DIM);
    k_tsplit<<<dim3(H_DIM / 32, H_DIM / 32), tb>>>(Wi1, nullptr, wi1hi, wi1lo, H_DIM, H_DIM);
    k_tsplit<<<dim3(I_DIM / 32, H_DIM / 32), tb>>>(Ws1, nullptr, ws1hi, ws1lo, I_DIM, H_DIM);

    // layer 0: pre0 = x @ (Wi0+Ws0)
    tc_gemm<<<dim3(H_DIM / 128, (T_DIM * B_DIM) / 128), 512, SM_TOTAL_BF16 * 2>>>(
        pre, x, I_DIM, w0hi, w0lo, nullptr, 0, nullptr, nullptr);

    k_reset_bar<<<1, 256>>>();
    recur5<<<128, 512, R5_BYTES>>>(pre, out, Wh0, hhi, hlo, T_DIM);

    // layer 1: pre1 = out0[1:] @ Wi1 + sx1 @ Ws1  (fused)
    int nsx = (T_DIM - 1) * B_DIM * I_DIM;
    k_sx1<<<(nsx + 255) / 256, 256>>>(x, sx1, nsx, B_DIM * I_DIM);
    tc_gemm<<<dim3(H_DIM / 128, ((T_DIM - 1) * B_DIM) / 128), 512, SM_TOTAL_BF16 * 2>>>(
        pre, out + BH, H_DIM, wi1hi, wi1lo, sx1, I_DIM, ws1hi, ws1lo);

    k_reset_bar<<<1, 256>>>();
    recur5<<<128, 512, R5_BYTES>>>(pre, out + (size_t)T_DIM * BH, Wh1, hhi, hlo, T_DIM - 1);
}

// round 13
// speedup vs baseline: 1.1157x; 1.1157x over previous
#include <cuda_runtime.h>
#include <cuda_bf16.h>
#include <cstdint>

// Problem constants
#define T_DIM 512
#define B_DIM 128
#define I_DIM 512
#define H_DIM 1024
#define BH (B_DIM * H_DIM)

// ---------------- scratch (static device globals: allocation-free) ----------
__device__ float g_pre[T_DIM * B_DIM * H_DIM];            // 268 MB, reused
__device__ float g_sx1[T_DIM * B_DIM * I_DIM];            // padded for 256-row GEMM tiles
__device__ unsigned g_bar4[4 * 64];                       // per-rowgroup barrier counters
// h state as pre-split bf16, double-buffered across steps
__device__ __nv_bfloat16 g_hhi[2 * BH], g_hlo[2 * BH];
// transposed + bf16-split weights: [N][K] row-major, K contiguous
__device__ __nv_bfloat16 g_w0t_hi[H_DIM * I_DIM], g_w0t_lo[H_DIM * I_DIM];
__device__ __nv_bfloat16 g_wi1t_hi[H_DIM * H_DIM], g_wi1t_lo[H_DIM * H_DIM];
__device__ __nv_bfloat16 g_ws1t_hi[H_DIM * I_DIM], g_ws1t_lo[H_DIM * I_DIM];

// ---------------- cp.async helpers -----------------------------------------
__device__ __forceinline__ void cp_async16(void* sdst, const void* gsrc) {
    unsigned s = (unsigned)__cvta_generic_to_shared(sdst);
    asm volatile("cp.async.cg.shared.global [%0], [%1], 16;" :: "r"(s), "l"(gsrc));
}
__device__ __forceinline__ void cp_commit() {
    asm volatile("cp.async.commit_group;" ::: "memory");
}
template <int N>
__device__ __forceinline__ void cp_wait() {
    asm volatile("cp.async.wait_group %0;" :: "n"(N) : "memory");
}

__device__ __forceinline__ void mma_bf16(float* c, const uint32_t* a, const uint32_t* b) {
    asm volatile(
        "mma.sync.aligned.m16n8k16.row.col.f32.bf16.bf16.f32 "
        "{%0,%1,%2,%3}, {%4,%5,%6,%7}, {%8,%9}, {%0,%1,%2,%3};"
        : "+f"(c[0]), "+f"(c[1]), "+f"(c[2]), "+f"(c[3])
        : "r"(a[0]), "r"(a[1]), "r"(a[2]), "r"(a[3]), "r"(b[0]), "r"(b[1]));
}

// ---------------- small elementwise kernels --------------------------------
__global__ void k_sx1(const float* __restrict__ x, float* __restrict__ o,
                      int n, int off) {
    int i = blockIdx.x * 256 + threadIdx.x;
    if (i < n) o[i] = 0.5f * (x[i] + x[i + off]);
}
__global__ void k_reset_bar() {
    if (threadIdx.x < 4 * 64) g_bar4[threadIdx.x] = 0u;
}

// transpose + bf16 hi/lo split: W[K,N] (+optional W2) -> Thi/Tlo [N,K]
__global__ void k_tsplit(const float* __restrict__ W, const float* __restrict__ W2,
                         __nv_bfloat16* __restrict__ Thi, __nv_bfloat16* __restrict__ Tlo,
                         int K, int N) {
    __shared__ float s[32][33];
    int k0 = blockIdx.x * 32, n0 = blockIdx.y * 32;
    int tx = threadIdx.x, ty = threadIdx.y;   // 32 x 8
#pragma unroll
    for (int i = 0; i < 4; i++) {
        int k = k0 + ty + i * 8;
        float v = W[(size_t)k * N + n0 + tx];
        if (W2) v += W2[(size_t)k * N + n0 + tx];
        s[ty + i * 8][tx] = v;
    }
    __syncthreads();
#pragma unroll
    for (int i = 0; i < 4; i++) {
        int n = n0 + ty + i * 8;
        float v = s[tx][ty + i * 8];
        __nv_bfloat16 h = __float2bfloat16(v);
        Thi[(size_t)n * K + k0 + tx] = h;
        Tlo[(size_t)n * K + k0 + tx] = __float2bfloat16(v - __bfloat162float(h));
    }
}

// ---------------- HMMA split-bf16 GEMM: block 256x128, 16 warps 64x32 -------
#define PITCH 40
#define ATILE (256 * PITCH)                 // A hi or lo tile (elems)
#define BTILE (128 * PITCH)                 // B hi or lo tile (elems)
#define SM_A 0
#define SM_B (4 * ATILE)
#define GEMM_SMEM_BYTES ((4 * ATILE + 4 * BTILE) * 2)   // 122880

__global__ __launch_bounds__(512) void tc_gemm(
    float* __restrict__ C,
    const float* __restrict__ A0, int K0,
    const __nv_bfloat16* __restrict__ B0hi, const __nv_bfloat16* __restrict__ B0lo,
    const float* __restrict__ A1, int K1,
    const __nv_bfloat16* __restrict__ B1hi, const __nv_bfloat16* __restrict__ B1lo)
{
    extern __shared__ __align__(16) __nv_bfloat16 sm[];
    const int tid = threadIdx.x;
    const int wid = tid >> 5, lane = tid & 31;
    const int g = lane >> 2, tg = lane & 3;
    const int wm = (wid >> 2) * 64, wn = (wid & 3) * 32;   // 4m x 4n warps
    const int mrow0 = blockIdx.y * 256;
    const int ncol0 = blockIdx.x * 128;

    const int NI0 = K0 / 32;
    const int NI = NI0 + K1 / 32;

    float acc[4][4][4];
#pragma unroll
    for (int i = 0; i < 4; i++)
#pragma unroll
        for (int j = 0; j < 4; j++)
#pragma unroll
            for (int q = 0; q < 4; q++) acc[i][j][q] = 0.f;

    // A-fill: 256 rows x 32 floats, 2 threads/row, 16 floats each
    const int ar = tid >> 1, ah = (tid & 1) * 16;
    // B-fill: hl = tid>>8, row = (tid&255)>>1, 2 x 16B segs per thread
    const int bhl = tid >> 8, br = (tid & 255) >> 1, bseg = (tid & 1) * 16;

#define A_SRC(A, K, koff) ((const float4*)((A) + (size_t)(mrow0 + ar) * (K) + (koff) + ah))
#define STS_A(buf, st)                                                                 \
    {                                                                                  \
        __nv_bfloat16* dh = sm + SM_A + ((buf) * 2 + 0) * ATILE + ar * PITCH + ah;     \
        __nv_bfloat16* dl = sm + SM_A + ((buf) * 2 + 1) * ATILE + ar * PITCH + ah;     \
        _Pragma("unroll")                                                              \
        for (int q = 0; q < 4; q++) {                                                  \
            float f[4] = {st[q].x, st[q].y, st[q].z, st[q].w};                         \
            uint32_t hi2[2], lo2[2];                                                   \
            _Pragma("unroll")                                                          \
            for (int j = 0; j < 2; j++) {                                              \
                __nv_bfloat16 h0 = __float2bfloat16(f[2 * j]);                         \
                __nv_bfloat16 h1 = __float2bfloat16(f[2 * j + 1]);                     \
                __nv_bfloat16 l0 = __float2bfloat16(f[2 * j] - __bfloat162float(h0));  \
                __nv_bfloat16 l1 = __float2bfloat16(f[2 * j + 1] - __bfloat162float(h1)); \
                hi2[j] = (uint32_t)__bfloat16_as_ushort(h0) |                          \
                         ((uint32_t)__bfloat16_as_ushort(h1) << 16);                   \
                lo2[j] = (uint32_t)__bfloat16_as_ushort(l0) |                          \
                         ((uint32_t)__bfloat16_as_ushort(l1) << 16);                   \
            }                                                                          \
            *(uint2*)(dh + q * 4) = make_uint2(hi2[0], hi2[1]);                        \
            *(uint2*)(dl + q * 4) = make_uint2(lo2[0], lo2[1]);                        \
        }                                                                              \
    }
#define LOAD_B(buf, Bhi, Blo, K, koff)                                                 \
    {                                                                                  \
        const __nv_bfloat16* src = ((bhl) ? (Blo) : (Bhi)) +                           \
                                   (size_t)(ncol0 + br) * (K) + (koff) + bseg;         \
        __nv_bfloat16* dst = sm + SM_B + ((buf) * 2 + bhl) * BTILE + br * PITCH +      \
                             bseg;                                                     \
        cp_async16(dst, src);                                                          \
        cp_async16(dst + 8, src + 8);                                                  \
    }

    {
        float4 st[4];
        const float4* s4 = A_SRC(A0, K0, 0);
#pragma unroll
        for (int q = 0; q < 4; q++) st[q] = s4[q];
        STS_A(0, st);
        LOAD_B(0, B0hi, B0lo, K0, 0);
        cp_commit();
    }

    for (int i = 0; i < NI; i++) {
        cp_wait<0>();
        __syncthreads();

        const int buf = i & 1;
        float4 st[4];
        bool have_next = (i + 1 < NI);
        if (have_next) {
            int ni = i + 1;
            if (ni < NI0) {
                const float4* s4 = A_SRC(A0, K0, ni * 32);
#pragma unroll
                for (int q = 0; q < 4; q++) st[q] = s4[q];
                LOAD_B(buf ^ 1, B0hi, B0lo, K0, ni * 32);
            } else {
                int koff = (ni - NI0) * 32;
                const float4* s4 = A_SRC(A1, K1, koff);
#pragma unroll
                for (int q = 0; q < 4; q++) st[q] = s4[q];
                LOAD_B(buf ^ 1, B1hi, B1lo, K1, koff);
            }
            cp_commit();
        }

        const __nv_bfloat16* sAh = sm + SM_A + (buf * 2 + 0) * ATILE;
        const __nv_bfloat16* sAl = sm + SM_A + (buf * 2 + 1) * ATILE;
        const __nv_bfloat16* sBh = sm + SM_B + (buf * 2 + 0) * BTILE;
        const __nv_bfloat16* sBl = sm + SM_B + (buf * 2 + 1) * BTILE;
#pragma unroll
        for (int kk = 0; kk < 32; kk += 16) {
            uint32_t bh[4][2], bl[4][2];
#pragma unroll
            for (int nt = 0; nt < 4; nt++) {
                int n = wn + nt * 8 + g;
                bh[nt][0] = *(const uint32_t*)(sBh + n * PITCH + kk + tg * 2);
                bh[nt][1] = *(const uint32_t*)(sBh + n * PITCH + kk + tg * 2 + 8);
                bl[nt][0] = *(const uint32_t*)(sBl + n * PITCH + kk + tg * 2);
                bl[nt][1] = *(const uint32_t*)(sBl + n * PITCH + kk + tg * 2 + 8);
            }
#pragma unroll
            for (int mt = 0; mt < 4; mt++) {
                int r = wm + mt * 16 + g;
                uint32_t a_hi[4], a_lo[4];
                a_hi[0] = *(const uint32_t*)(sAh + r * PITCH + kk + tg * 2);
                a_hi[1] = *(const uint32_t*)(sAh + (r + 8) * PITCH + kk + tg * 2);
                a_hi[2] = *(const uint32_t*)(sAh + r * PITCH + kk + tg * 2 + 8);
                a_hi[3] = *(const uint32_t*)(sAh + (r + 8) * PITCH + kk + tg * 2 + 8);
                a_lo[0] = *(const uint32_t*)(sAl + r * PITCH + kk + tg * 2);
                a_lo[1] = *(const uint32_t*)(sAl + (r + 8) * PITCH + kk + tg * 2);
                a_lo[2] = *(const uint32_t*)(sAl + r * PITCH + kk + tg * 2 + 8);
                a_lo[3] = *(const uint32_t*)(sAl + (r + 8) * PITCH + kk + tg * 2 + 8);
#pragma unroll
                for (int nt = 0; nt < 4; nt++) {
                    mma_bf16(acc[mt][nt], a_hi, bh[nt]);
                    mma_bf16(acc[mt][nt], a_lo, bh[nt]);
                    mma_bf16(acc[mt][nt], a_hi, bl[nt]);
                }
            }
        }

        if (have_next) STS_A(buf ^ 1, st);
    }

#pragma unroll
    for (int mt = 0; mt < 4; mt++) {
#pragma unroll
        for (int nt = 0; nt < 4; nt++) {
            int r0 = mrow0 + wm + mt * 16 + g;
            int c0 = ncol0 + wn + nt * 8 + tg * 2;
            *(float2*)(C + (size_t)r0 * 1024 + c0) =
                make_float2(acc[mt][nt][0], acc[mt][nt][1]);
            *(float2*)(C + (size_t)(r0 + 8) * 1024 + c0) =
                make_float2(acc[mt][nt][2], acc[mt][nt][3]);
        }
    }
#undef A_SRC
#undef STS_A
#undef LOAD_B
}

// ---------------- HMMA persistent recurrence v3 (R8/R10, proven) ------------
#define R3_WP 1032
#define R3_SW (32 * R3_WP)
#define R3_HP 264
#define R3_HB (32 * R3_HP)
#define R3_HOFF (2 * R3_SW)
#define R3_RED_BYTE (R3_HOFF * 2)
#define R3_RPITCH 34
#define R3_RW (32 * R3_RPITCH)
#define R3_PRE_BYTE ((R3_HOFF + 4 * R3_HB) * 2)
#define R3_BYTES (R3_PRE_BYTE + 4096)

__global__ __launch_bounds__(256, 1) void recur3(
    const float* __restrict__ pre, float* __restrict__ out,
    const float* __restrict__ Wh,
    __nv_bfloat16* __restrict__ hhi, __nv_bfloat16* __restrict__ hlo,
    int steps)
{
    extern __shared__ __align__(16) __nv_bfloat16 sm2[];
    float* red  = (float*)((char*)sm2 + R3_RED_BYTE);
    float* preS = (float*)((char*)sm2 + R3_PRE_BYTE);
    const int tid = threadIdx.x, wid = tid >> 5, lane = tid & 31;
    const int g = lane >> 2, tg = lane & 3;
    const int rg = blockIdx.x >> 5;
    const int r0 = rg * 32;
    const int c0 = (blockIdx.x & 31) * 32;

    for (int k = wid; k < H_DIM; k += 8) {
        float w = Wh[(size_t)k * H_DIM + c0 + lane];
        __nv_bfloat16 h = __float2bfloat16(w);
        sm2[lane * R3_WP + k] = h;
        sm2[R3_SW + lane * R3_WP + k] = __float2bfloat16(w - __bfloat162float(h));
    }
    __syncthreads();

    unsigned target = 0;
    volatile unsigned* vb = &g_bar4[rg * 64];

#define ISSUE_H(c, buf, hp)                                                              \
    {                                                                                    \
        _Pragma("unroll")                                                                \
        for (int i = 0; i < 8; i++) {                                                    \
            int f = i * 256 + tid;                                                       \
            int hl = f >> 10, rem = f & 1023;                                            \
            int row = rem >> 5, seg = rem & 31;                                          \
            const __nv_bfloat16* src = (hl ? hlo : hhi) + (size_t)(hp)*BH +              \
                                       (size_t)(r0 + row) * H_DIM + (c)*256 + seg * 8;   \
            cp_async16(sm2 + R3_HOFF + ((buf)*2 + hl) * R3_HB + row * R3_HP + seg * 8,   \
                       src);                                                             \
        }                                                                                \
        cp_commit();                                                                     \
    }
#define ISSUE_PRE(tt)                                                                    \
    {                                                                                    \
        int row = tid >> 3, seg = tid & 7;                                               \
        cp_async16(preS + row * 32 + seg * 4,                                            \
                   pre + (size_t)(tt)*BH + (size_t)(r0 + row) * H_DIM + c0 + seg * 4);   \
        cp_commit();                                                                     \
    }

    for (int t = 0; t < steps; t++) {
        float acc[2][4][4];
#pragma unroll
        for (int mt = 0; mt < 2; mt++)
#pragma unroll
            for (int nt = 0; nt < 4; nt++)
#pragma unroll
                for (int q = 0; q < 4; q++) acc[mt][nt][q] = 0.f;

        if (t > 0) {
            const int hp = (t - 1) & 1;
            ISSUE_H(0, 0, hp);
            ISSUE_H(1, 1, hp);
            ISSUE_PRE(t);
#pragma unroll 1
            for (int c = 0; c < 4; c++) {
                if (c <= 1) cp_wait<2>();
                else if (c == 2) cp_wait<1>();
                else cp_wait<0>();
                __syncthreads();
                const int buf = c & 1;
                const __nv_bfloat16* sAh = sm2 + R3_HOFF + buf * 2 * R3_HB;
                const __nv_bfloat16* sAl = sAh + R3_HB;
                const int kl = wid * 32;
#pragma unroll
                for (int kt = 0; kt < 2; kt++) {
                    const int kk = kl + kt * 16;
                    const int kgl = c * 256 + kk;
                    uint32_t ah[2][4], al[2][4];
#pragma unroll
                    for (int mt = 0; mt < 2; mt++) {
                        const int ra = (mt * 16 + g) * R3_HP + kk + tg * 2;
                        const int rb = (mt * 16 + g + 8) * R3_HP + kk + tg * 2;
                        ah[mt][0] = *(const uint32_t*)(sAh + ra);
                        ah[mt][1] = *(const uint32_t*)(sAh + rb);
                        ah[mt][2] = *(const uint32_t*)(sAh + ra + 8);
                        ah[mt][3] = *(const uint32_t*)(sAh + rb + 8);
                        al[mt][0] = *(const uint32_t*)(sAl + ra);
                        al[mt][1] = *(const uint32_t*)(sAl + rb);
                        al[mt][2] = *(const uint32_t*)(sAl + ra + 8);
                        al[mt][3] = *(const uint32_t*)(sAl + rb + 8);
                    }
#pragma unroll
                    for (int nt = 0; nt < 4; nt++) {
                        const int nb = (nt * 8 + g) * R3_WP + kgl + tg * 2;
                        uint32_t bh[2], bl[2];
                        bh[0] = *(const uint32_t*)(sm2 + nb);
                        bh[1] = *(const uint32_t*)(sm2 + nb + 8);
                        bl[0] = *(const uint32_t*)(sm2 + R3_SW + nb);
                        bl[1] = *(const uint32_t*)(sm2 + R3_SW + nb + 8);
#pragma unroll
                        for (int mt = 0; mt < 2; mt++) {
                            mma_bf16(acc[mt][nt], ah[mt], bh);
                            mma_bf16(acc[mt][nt], al[mt], bh);
                            mma_bf16(acc[mt][nt], ah[mt], bl);
                        }
                    }
                }
                __syncthreads();
                if (c < 2) ISSUE_H(c + 2, c & 1, hp);
            }
            float* rw = red + wid * R3_RW;
#pragma unroll
            for (int mt = 0; mt < 2; mt++)
#pragma unroll
                for (int nt = 0; nt < 4; nt++) {
                    int row = mt * 16 + g, col = nt * 8 + tg * 2;
                    *(float2*)(rw + row * R3_RPITCH + col) =
                        make_float2(acc[mt][nt][0], acc[mt][nt][1]);
                    *(float2*)(rw + (row + 8) * R3_RPITCH + col) =
                        make_float2(acc[mt][nt][2], acc[mt][nt][3]);
                }
            __syncthreads();
        } else {
            ISSUE_PRE(0);
            cp_wait<0>();
            __syncthreads();
        }

        {
            const int row = tid >> 3, cseg = (tid & 7) * 4;
            float4 s = make_float4(0.f, 0.f, 0.f, 0.f);
            if (t > 0) {
#pragma unroll
                for (int w = 0; w < 8; w++) {
                    const float* rp = red + w * R3_RW + row * R3_RPITCH + cseg;
                    s.x += rp[0]; s.y += rp[1]; s.z += rp[2]; s.w += rp[3];
                }
            }
            const float4 p = *(const float4*)(preS + row * 32 + cseg);
            float v0 = tanhf(p.x + s.x), v1 = tanhf(p.y + s.y);
            float v2 = tanhf(p.z + s.z), v3 = tanhf(p.w + s.w);
            const size_t gidx = (size_t)(r0 + row) * H_DIM + c0 + cseg;
            *(float4*)(out + (size_t)t * BH + gidx) = make_float4(v0, v1, v2, v3);

            __nv_bfloat16 h0 = __float2bfloat16(v0), h1 = __float2bfloat16(v1);
            __nv_bfloat16 h2 = __float2bfloat16(v2), h3 = __float2bfloat16(v3);
            __nv_bfloat16 l0 = __float2bfloat16(v0 - __bfloat162float(h0));
            __nv_bfloat16 l1 = __float2bfloat16(v1 - __bfloat162float(h1));
            __nv_bfloat16 l2 = __float2bfloat16(v2 - __bfloat162float(h2));
            __nv_bfloat16 l3 = __float2bfloat16(v3 - __bfloat162float(h3));
            const size_t hidx = (size_t)(t & 1) * BH + gidx;
            *(uint2*)(hhi + hidx) = make_uint2(
                (uint32_t)__bfloat16_as_ushort(h0) | ((uint32_t)__bfloat16_as_ushort(h1) << 16),
                (uint32_t)__bfloat16_as_ushort(h2) | ((uint32_t)__bfloat16_as_ushort(h3) << 16));
            *(uint2*)(hlo + hidx) = make_uint2(
                (uint32_t)__bfloat16_as_ushort(l0) | ((uint32_t)__bfloat16_as_ushort(l1) << 16),
                (uint32_t)__bfloat16_as_ushort(l2) | ((uint32_t)__bfloat16_as_ushort(l3) << 16));
        }

        if (t + 1 < steps) {
            __threadfence();
            __syncthreads();
            target += 32;
            if (tid == 0) {
                atomicAdd((unsigned*)vb, 1u);
                while (*vb < target) __nanosleep(32);
            }
            __syncthreads();
        }
    }
#undef ISSUE_H
#undef ISSUE_PRE
}

// ---------------- launch ----------------------------------------------------
extern "C" void kernel_launch(void* const* d_in, const int* in_sizes, int n_in,
                              void* d_out, int out_size)
{
    (void)in_sizes; (void)n_in; (void)out_size;
    const float* x   = (const float*)d_in[0];
    const float* Wi0 = (const float*)d_in[1];
    const float* Wh0 = (const float*)d_in[2];
    const float* Ws0 = (const float*)d_in[3];
    const float* Wi1 = (const float*)d_in[4];
    const float* Wh1 = (const float*)d_in[5];
    const float* Ws1 = (const float*)d_in[6];
    float* out = (float*)d_out;

    void* p;
    cudaGetSymbolAddress(&p, g_pre);     float* pre = (float*)p;
    cudaGetSymbolAddress(&p, g_sx1);     float* sx1 = (float*)p;
    cudaGetSymbolAddress(&p, g_hhi);     __nv_bfloat16* hhi = (__nv_bfloat16*)p;
    cudaGetSymbolAddress(&p, g_hlo);     __nv_bfloat16* hlo = (__nv_bfloat16*)p;
    cudaGetSymbolAddress(&p, g_w0t_hi);  __nv_bfloat16* w0hi = (__nv_bfloat16*)p;
    cudaGetSymbolAddress(&p, g_w0t_lo);  __nv_bfloat16* w0lo = (__nv_bfloat16*)p;
    cudaGetSymbolAddress(&p, g_wi1t_hi); __nv_bfloat16* wi1hi = (__nv_bfloat16*)p;
    cudaGetSymbolAddress(&p, g_wi1t_lo); __nv_bfloat16* wi1lo = (__nv_bfloat16*)p;
    cudaGetSymbolAddress(&p, g_ws1t_hi); __nv_bfloat16* ws1hi = (__nv_bfloat16*)p;
    cudaGetSymbolAddress(&p, g_ws1t_lo); __nv_bfloat16* ws1lo = (__nv_bfloat16*)p;

    cudaFuncSetAttribute(recur3,
                         cudaFuncAttributeMaxDynamicSharedMemorySize, R3_BYTES);
    cudaFuncSetAttribute(tc_gemm,
                         cudaFuncAttributeMaxDynamicSharedMemorySize,
                         GEMM_SMEM_BYTES);

    // weight prep: transpose + bf16 hi/lo split
    dim3 tb(32, 8);
    k_tsplit<<<dim3(I_DIM / 32, H_DIM / 32), tb>>>(Wi0, Ws0, w0hi, w0lo, I_DIM, H_DIM);
    k_tsplit<<<dim3(H_DIM / 32, H_DIM / 32), tb>>>(Wi1, nullptr, wi1hi, wi1lo, H_DIM, H_DIM);
    k_tsplit<<<dim3(I_DIM / 32, H_DIM / 32), tb>>>(Ws1, nullptr, ws1hi, ws1lo, I_DIM, H_DIM);

    // layer 0: pre0 = x @ (Wi0+Ws0)   (M = 65536 = 256 * 256)
    tc_gemm<<<dim3(H_DIM / 128, (T_DIM * B_DIM) / 256), 512, GEMM_SMEM_BYTES>>>(
        pre, x, I_DIM, w0hi, w0lo, nullptr, 0, nullptr, nullptr);

    k_reset_bar<<<1, 256>>>();
    recur3<<<128, 256, R3_BYTES>>>(pre, out, Wh0, hhi, hlo, T_DIM);

    // layer 1: pre1 = out0[1:] @ Wi1 + sx1 @ Ws1  (fused)
    // M = 65408 padded to 65536 (256 row-blocks); padded rows read in-bounds
    // garbage (g_sx1 padded; out region large enough) and write pre rows that
    // no recurrence step consumes.
    int nsx = (T_DIM - 1) * B_DIM * I_DIM;
    k_sx1<<<(nsx + 255) / 256, 256>>>(x, sx1, nsx, B_DIM * I_DIM);
    tc_gemm<<<dim3(H_DIM / 128, (T_DIM * B_DIM) / 256), 512, GEMM_SMEM_BYTES>>>(
        pre, out + BH, H_DIM, wi1hi, wi1lo, sx1, I_DIM, ws1hi, ws1lo);

    k_reset_bar<<<1, 256>>>();
    recur3<<<128, 256, R3_BYTES>>>(pre, out + (size_t)T_DIM * BH, Wh1, hhi, hlo, T_DIM - 1);
}

// round 14
// speedup vs baseline: 1.1374x; 1.0194x over previous
#include <cuda_runtime.h>
#include <cuda_bf16.h>
#include <cstdint>

// Problem constants
#define T_DIM 512
#define B_DIM 128
#define I_DIM 512
#define H_DIM 1024
#define BH (B_DIM * H_DIM)

// ---------------- scratch (static device globals: allocation-free) ----------
__device__ float g_pre[T_DIM * B_DIM * H_DIM];            // 268 MB, reused
__device__ unsigned g_bar4[4 * 64];                       // per-rowgroup barrier counters
// pre-split activations (bf16 hi/lo)
__device__ __nv_bfloat16 g_x_hi[T_DIM * B_DIM * I_DIM], g_x_lo[T_DIM * B_DIM * I_DIM];
__device__ __nv_bfloat16 g_sx1_hi[(T_DIM - 1) * B_DIM * I_DIM];
__device__ __nv_bfloat16 g_sx1_lo[(T_DIM - 1) * B_DIM * I_DIM];
// h state as pre-split bf16, FULL time series (doubles as layer-1 GEMM A operand)
__device__ __nv_bfloat16 g_hf_hi[T_DIM * BH], g_hf_lo[T_DIM * BH];
// transposed + bf16-split weights: [N][K] row-major, K contiguous
__device__ __nv_bfloat16 g_w0t_hi[H_DIM * I_DIM], g_w0t_lo[H_DIM * I_DIM];
__device__ __nv_bfloat16 g_wi1t_hi[H_DIM * H_DIM], g_wi1t_lo[H_DIM * H_DIM];
__device__ __nv_bfloat16 g_ws1t_hi[H_DIM * I_DIM], g_ws1t_lo[H_DIM * I_DIM];

// ---------------- cp.async helpers -----------------------------------------
__device__ __forceinline__ void cp_async16(void* sdst, const void* gsrc) {
    unsigned s = (unsigned)__cvta_generic_to_shared(sdst);
    asm volatile("cp.async.cg.shared.global [%0], [%1], 16;" :: "r"(s), "l"(gsrc));
}
__device__ __forceinline__ void cp_commit() {
    asm volatile("cp.async.commit_group;" ::: "memory");
}
template <int N>
__device__ __forceinline__ void cp_wait() {
    asm volatile("cp.async.wait_group %0;" :: "n"(N) : "memory");
}

__device__ __forceinline__ void mma_bf16(float* c, const uint32_t* a, const uint32_t* b) {
    asm volatile(
        "mma.sync.aligned.m16n8k16.row.col.f32.bf16.bf16.f32 "
        "{%0,%1,%2,%3}, {%4,%5,%6,%7}, {%8,%9}, {%0,%1,%2,%3};"
        : "+f"(c[0]), "+f"(c[1]), "+f"(c[2]), "+f"(c[3])
        : "r"(a[0]), "r"(a[1]), "r"(a[2]), "r"(a[3]), "r"(b[0]), "r"(b[1]));
}

// ---------------- small elementwise kernels --------------------------------
__global__ void k_xsplit(const float* __restrict__ x,
                         __nv_bfloat16* __restrict__ hi, __nv_bfloat16* __restrict__ lo,
                         int n) {
    int i = blockIdx.x * 256 + threadIdx.x;
    if (i < n) {
        float v = x[i];
        __nv_bfloat16 h = __float2bfloat16(v);
        hi[i] = h;
        lo[i] = __float2bfloat16(v - __bfloat162float(h));
    }
}
__global__ void k_sx1(const float* __restrict__ x,
                      __nv_bfloat16* __restrict__ ohi, __nv_bfloat16* __restrict__ olo,
                      int n, int off) {
    int i = blockIdx.x * 256 + threadIdx.x;
    if (i < n) {
        float v = 0.5f * (x[i] + x[i + off]);
        __nv_bfloat16 h = __float2bfloat16(v);
        ohi[i] = h;
        olo[i] = __float2bfloat16(v - __bfloat162float(h));
    }
}
__global__ void k_reset_bar() {
    if (threadIdx.x < 4 * 64) g_bar4[threadIdx.x] = 0u;
}

// transpose + bf16 hi/lo split: W[K,N] (+optional W2) -> Thi/Tlo [N,K]
__global__ void k_tsplit(const float* __restrict__ W, const float* __restrict__ W2,
                         __nv_bfloat16* __restrict__ Thi, __nv_bfloat16* __restrict__ Tlo,
                         int K, int N) {
    __shared__ float s[32][33];
    int k0 = blockIdx.x * 32, n0 = blockIdx.y * 32;
    int tx = threadIdx.x, ty = threadIdx.y;   // 32 x 8
#pragma unroll
    for (int i = 0; i < 4; i++) {
        int k = k0 + ty + i * 8;
        float v = W[(size_t)k * N + n0 + tx];
        if (W2) v += W2[(size_t)k * N + n0 + tx];
        s[ty + i * 8][tx] = v;
    }
    __syncthreads();
#pragma unroll
    for (int i = 0; i < 4; i++) {
        int n = n0 + ty + i * 8;
        float v = s[tx][ty + i * 8];
        __nv_bfloat16 h = __float2bfloat16(v);
        Thi[(size_t)n * K + k0 + tx] = h;
        Tlo[(size_t)n * K + k0 + tx] = __float2bfloat16(v - __bfloat162float(h));
    }
}

// ---------------- HMMA GEMM v2: all-bf16 operands, pure cp.async ------------
// C[M,1024] = A0[M,K0] @ B0^T (+ A1[M,K1] @ B1^T). A and B pre-split bf16,
// row-major [rows][K]. Block 128x128x32, 512 thr, warp tile 32x32 (R10 shape).
#define PITCH 40
#define TILE_HL (128 * PITCH)
#define SM_A 0
#define SM_B (4 * TILE_HL)
#define GEMM_SMEM_BYTES (8 * TILE_HL * 2)      // 81920

__global__ __launch_bounds__(512) void tc_gemm(
    float* __restrict__ C,
    const __nv_bfloat16* __restrict__ A0hi, const __nv_bfloat16* __restrict__ A0lo, int K0,
    const __nv_bfloat16* __restrict__ B0hi, const __nv_bfloat16* __restrict__ B0lo,
    const __nv_bfloat16* __restrict__ A1hi, const __nv_bfloat16* __restrict__ A1lo, int K1,
    const __nv_bfloat16* __restrict__ B1hi, const __nv_bfloat16* __restrict__ B1lo)
{
    extern __shared__ __align__(16) __nv_bfloat16 sm[];
    const int tid = threadIdx.x;
    const int wid = tid >> 5, lane = tid & 31;
    const int g = lane >> 2, tg = lane & 3;
    const int wm = (wid >> 2) * 32, wn = (wid & 3) * 32;
    const int mrow0 = blockIdx.y * 128;
    const int ncol0 = blockIdx.x * 128;

    const int NI0 = K0 / 32;
    const int NI = NI0 + K1 / 32;

    float acc[2][4][4];
#pragma unroll
    for (int i = 0; i < 2; i++)
#pragma unroll
        for (int j = 0; j < 4; j++)
#pragma unroll
            for (int q = 0; q < 4; q++) acc[i][j][q] = 0.f;

    // loader mapping: msel 0=A,1=B; within 256: seg(4) x hl(2) x rowbase(32),
    // 4 issues advance row by 32 -> per-instr 4 rows x 2 hl x 64B runs.
    const int msel = tid >> 8;
    const int lq = tid & 255;
    const int lseg = (lq & 3) * 8;            // elem offset of 16B seg
    const int lhl = (lq >> 2) & 1;
    const int lrb = lq >> 3;                  // 0..31

#define LOAD_AB(buf, Ahi, Alo, Bhi, Blo, K, koff)                                      \
    {                                                                                  \
        const __nv_bfloat16* bse = msel ? ((lhl) ? (Blo) : (Bhi))                      \
                                        : ((lhl) ? (Alo) : (Ahi));                     \
        const int rb0 = msel ? ncol0 : mrow0;                                          \
        __nv_bfloat16* dbase = sm + (msel ? SM_B : SM_A) + ((buf)*2 + lhl) * TILE_HL;  \
        _Pragma("unroll")                                                              \
        for (int i = 0; i < 4; i++) {                                                  \
            int r = lrb + i * 32;                                                      \
            cp_async16(dbase + r * PITCH + lseg,                                       \
                       bse + (size_t)(rb0 + r) * (K) + (koff) + lseg);                 \
        }                                                                              \
        cp_commit();                                                                   \
    }

    LOAD_AB(0, A0hi, A0lo, B0hi, B0lo, K0, 0);

    for (int i = 0; i < NI; i++) {
        cp_wait<0>();
        __syncthreads();

        const int buf = i & 1;
        if (i + 1 < NI) {
            int ni = i + 1;
            if (ni < NI0) {
                LOAD_AB(buf ^ 1, A0hi, A0lo, B0hi, B0lo, K0, ni * 32);
            } else {
                LOAD_AB(buf ^ 1, A1hi, A1lo, B1hi, B1lo, K1, (ni - NI0) * 32);
            }
        }

        const __nv_bfloat16* sAh = sm + SM_A + (buf * 2 + 0) * TILE_HL;
        const __nv_bfloat16* sAl = sm + SM_A + (buf * 2 + 1) * TILE_HL;
        const __nv_bfloat16* sBh = sm + SM_B + (buf * 2 + 0) * TILE_HL;
        const __nv_bfloat16* sBl = sm + SM_B + (buf * 2 + 1) * TILE_HL;
#pragma unroll
        for (int kk = 0; kk < 32; kk += 16) {
            uint32_t bh[4][2], bl[4][2];
#pragma unroll
            for (int nt = 0; nt < 4; nt++) {
                int n = wn + nt * 8 + g;
                bh[nt][0] = *(const uint32_t*)(sBh + n * PITCH + kk + tg * 2);
                bh[nt][1] = *(const uint32_t*)(sBh + n * PITCH + kk + tg * 2 + 8);
                bl[nt][0] = *(const uint32_t*)(sBl + n * PITCH + kk + tg * 2);
                bl[nt][1] = *(const uint32_t*)(sBl + n * PITCH + kk + tg * 2 + 8);
            }
#pragma unroll
            for (int mt = 0; mt < 2; mt++) {
                int r = wm + mt * 16 + g;
                uint32_t a_hi[4], a_lo[4];
                a_hi[0] = *(const uint32_t*)(sAh + r * PITCH + kk + tg * 2);
                a_hi[1] = *(const uint32_t*)(sAh + (r + 8) * PITCH + kk + tg * 2);
                a_hi[2] = *(const uint32_t*)(sAh + r * PITCH + kk + tg * 2 + 8);
                a_hi[3] = *(const uint32_t*)(sAh + (r + 8) * PITCH + kk + tg * 2 + 8);
                a_lo[0] = *(const uint32_t*)(sAl + r * PITCH + kk + tg * 2);
                a_lo[1] = *(const uint32_t*)(sAl + (r + 8) * PITCH + kk + tg * 2);
                a_lo[2] = *(const uint32_t*)(sAl + r * PITCH + kk + tg * 2 + 8);
                a_lo[3] = *(const uint32_t*)(sAl + (r + 8) * PITCH + kk + tg * 2 + 8);
#pragma unroll
                for (int nt = 0; nt < 4; nt++) {
                    mma_bf16(acc[mt][nt], a_hi, bh[nt]);
                    mma_bf16(acc[mt][nt], a_lo, bh[nt]);
                    mma_bf16(acc[mt][nt], a_hi, bl[nt]);
                }
            }
        }
    }

#pragma unroll
    for (int mt = 0; mt < 2; mt++) {
#pragma unroll
        for (int nt = 0; nt < 4; nt++) {
            int r0 = mrow0 + wm + mt * 16 + g;
            int c0 = ncol0 + wn + nt * 8 + tg * 2;
            *(float2*)(C + (size_t)r0 * 1024 + c0) =
                make_float2(acc[mt][nt][0], acc[mt][nt][1]);
            *(float2*)(C + (size_t)(r0 + 8) * 1024 + c0) =
                make_float2(acc[mt][nt][2], acc[mt][nt][3]);
        }
    }
#undef LOAD_AB
}

// ---------------- HMMA persistent recurrence v3 (R8/R10 proven structure) ---
// Only change vs R10: h split state lives in a FULL time series (slice t),
// so layer-1's GEMM consumes it directly. Addressing change only.
#define R3_WP 1032
#define R3_SW (32 * R3_WP)
#define R3_HP 264
#define R3_HB (32 * R3_HP)
#define R3_HOFF (2 * R3_SW)
#define R3_RED_BYTE (R3_HOFF * 2)
#define R3_RPITCH 34
#define R3_RW (32 * R3_RPITCH)
#define R3_PRE_BYTE ((R3_HOFF + 4 * R3_HB) * 2)
#define R3_BYTES (R3_PRE_BYTE + 4096)

__global__ __launch_bounds__(256, 1) void recur3(
    const float* __restrict__ pre, float* __restrict__ out,
    const float* __restrict__ Wh,
    __nv_bfloat16* __restrict__ hhi, __nv_bfloat16* __restrict__ hlo,
    int steps)
{
    extern __shared__ __align__(16) __nv_bfloat16 sm2[];
    float* red  = (float*)((char*)sm2 + R3_RED_BYTE);
    float* preS = (float*)((char*)sm2 + R3_PRE_BYTE);
    const int tid = threadIdx.x, wid = tid >> 5, lane = tid & 31;
    const int g = lane >> 2, tg = lane & 3;
    const int rg = blockIdx.x >> 5;
    const int r0 = rg * 32;
    const int c0 = (blockIdx.x & 31) * 32;

    for (int k = wid; k < H_DIM; k += 8) {
        float w = Wh[(size_t)k * H_DIM + c0 + lane];
        __nv_bfloat16 h = __float2bfloat16(w);
        sm2[lane * R3_WP + k] = h;
        sm2[R3_SW + lane * R3_WP + k] = __float2bfloat16(w - __bfloat162float(h));
    }
    __syncthreads();

    unsigned target = 0;
    volatile unsigned* vb = &g_bar4[rg * 64];

#define ISSUE_H(c, buf, tt)                                                              \
    {                                                                                    \
        _Pragma("unroll")                                                                \
        for (int i = 0; i < 8; i++) {                                                    \
            int f = i * 256 + tid;                                                       \
            int hl = f >> 10, rem = f & 1023;                                            \
            int row = rem >> 5, seg = rem & 31;                                          \
            const __nv_bfloat16* src = (hl ? hlo : hhi) + (size_t)(tt)*BH +              \
                                       (size_t)(r0 + row) * H_DIM + (c)*256 + seg * 8;   \
            cp_async16(sm2 + R3_HOFF + ((buf)*2 + hl) * R3_HB + row * R3_HP + seg * 8,   \
                       src);                                                             \
        }                                                                                \
        cp_commit();                                                                     \
    }
#define ISSUE_PRE(tt)                                                                    \
    {                                                                                    \
        int row = tid >> 3, seg = tid & 7;                                               \
        cp_async16(preS + row * 32 + seg * 4,                                            \
                   pre + (size_t)(tt)*BH + (size_t)(r0 + row) * H_DIM + c0 + seg * 4);   \
        cp_commit();                                                                     \
    }

    for (int t = 0; t < steps; t++) {
        float acc[2][4][4];
#pragma unroll
        for (int mt = 0; mt < 2; mt++)
#pragma unroll
            for (int nt = 0; nt < 4; nt++)
#pragma unroll
                for (int q = 0; q < 4; q++) acc[mt][nt][q] = 0.f;

        if (t > 0) {
            ISSUE_H(0, 0, t - 1);
            ISSUE_H(1, 1, t - 1);
            ISSUE_PRE(t);
#pragma unroll 1
            for (int c = 0; c < 4; c++) {
                if (c <= 1) cp_wait<2>();
                else if (c == 2) cp_wait<1>();
                else cp_wait<0>();
                __syncthreads();
                const int buf = c & 1;
                const __nv_bfloat16* sAh = sm2 + R3_HOFF + buf * 2 * R3_HB;
                const __nv_bfloat16* sAl = sAh + R3_HB;
                const int kl = wid * 32;
#pragma unroll
                for (int kt = 0; kt < 2; kt++) {
                    const int kk = kl + kt * 16;
                    const int kgl = c * 256 + kk;
                    uint32_t ah[2][4], al[2][4];
#pragma unroll
                    for (int mt = 0; mt < 2; mt++) {
                        const int ra = (mt * 16 + g) * R3_HP + kk + tg * 2;
                        const int rb = (mt * 16 + g + 8) * R3_HP + kk + tg * 2;
                        ah[mt][0] = *(const uint32_t*)(sAh + ra);
                        ah[mt][1] = *(const uint32_t*)(sAh + rb);
                        ah[mt][2] = *(const uint32_t*)(sAh + ra + 8);
                        ah[mt][3] = *(const uint32_t*)(sAh + rb + 8);
                        al[mt][0] = *(const uint32_t*)(sAl + ra);
                        al[mt][1] = *(const uint32_t*)(sAl + rb);
                        al[mt][2] = *(const uint32_t*)(sAl + ra + 8);
                        al[mt][3] = *(const uint32_t*)(sAl + rb + 8);
                    }
#pragma unroll
                    for (int nt = 0; nt < 4; nt++) {
                        const int nb = (nt * 8 + g) * R3_WP + kgl + tg * 2;
                        uint32_t bh[2], bl[2];
                        bh[0] = *(const uint32_t*)(sm2 + nb);
                        bh[1] = *(const uint32_t*)(sm2 + nb + 8);
                        bl[0] = *(const uint32_t*)(sm2 + R3_SW + nb);
                        bl[1] = *(const uint32_t*)(sm2 + R3_SW + nb + 8);
#pragma unroll
                        for (int mt = 0; mt < 2; mt++) {
                            mma_bf16(acc[mt][nt], ah[mt], bh);
                            mma_bf16(acc[mt][nt], al[mt], bh);
                            mma_bf16(acc[mt][nt], ah[mt], bl);
                        }
                    }
                }
                __syncthreads();
                if (c < 2) ISSUE_H(c + 2, c & 1, t - 1);
            }
            float* rw = red + wid * R3_RW;
#pragma unroll
            for (int mt = 0; mt < 2; mt++)
#pragma unroll
                for (int nt = 0; nt < 4; nt++) {
                    int row = mt * 16 + g, col = nt * 8 + tg * 2;
                    *(float2*)(rw + row * R3_RPITCH + col) =
                        make_float2(acc[mt][nt][0], acc[mt][nt][1]);
                    *(float2*)(rw + (row + 8) * R3_RPITCH + col) =
                        make_float2(acc[mt][nt][2], acc[mt][nt][3]);
                }
            __syncthreads();
        } else {
            ISSUE_PRE(0);
            cp_wait<0>();
            __syncthreads();
        }

        {
            const int row = tid >> 3, cseg = (tid & 7) * 4;
            float4 s = make_float4(0.f, 0.f, 0.f, 0.f);
            if (t > 0) {
#pragma unroll
                for (int w = 0; w < 8; w++) {
                    const float* rp = red + w * R3_RW + row * R3_RPITCH + cseg;
                    s.x += rp[0]; s.y += rp[1]; s.z += rp[2]; s.w += rp[3];
                }
            }
            const float4 p = *(const float4*)(preS + row * 32 + cseg);
            float v0 = tanhf(p.x + s.x), v1 = tanhf(p.y + s.y);
            float v2 = tanhf(p.z + s.z), v3 = tanhf(p.w + s.w);
            const size_t gidx = (size_t)(r0 + row) * H_DIM + c0 + cseg;
            *(float4*)(out + (size_t)t * BH + gidx) = make_float4(v0, v1, v2, v3);

            __nv_bfloat16 h0 = __float2bfloat16(v0), h1 = __float2bfloat16(v1);
            __nv_bfloat16 h2 = __float2bfloat16(v2), h3 = __float2bfloat16(v3);
            __nv_bfloat16 l0 = __float2bfloat16(v0 - __bfloat162float(h0));
            __nv_bfloat16 l1 = __float2bfloat16(v1 - __bfloat162float(h1));
            __nv_bfloat16 l2 = __float2bfloat16(v2 - __bfloat162float(h2));
            __nv_bfloat16 l3 = __float2bfloat16(v3 - __bfloat162float(h3));
            const size_t hidx = (size_t)t * BH + gidx;
            *(uint2*)(hhi + hidx) = make_uint2(
                (uint32_t)__bfloat16_as_ushort(h0) | ((uint32_t)__bfloat16_as_ushort(h1) << 16),
                (uint32_t)__bfloat16_as_ushort(h2) | ((uint32_t)__bfloat16_as_ushort(h3) << 16));
            *(uint2*)(hlo + hidx) = make_uint2(
                (uint32_t)__bfloat16_as_ushort(l0) | ((uint32_t)__bfloat16_as_ushort(l1) << 16),
                (uint32_t)__bfloat16_as_ushort(l2) | ((uint32_t)__bfloat16_as_ushort(l3) << 16));
        }

        if (t + 1 < steps) {
            __threadfence();
            __syncthreads();
            target += 32;
            if (tid == 0) {
                atomicAdd((unsigned*)vb, 1u);
                while (*vb < target) __nanosleep(32);
            }
            __syncthreads();
        }
    }
#undef ISSUE_H
#undef ISSUE_PRE
}

// ---------------- launch ----------------------------------------------------
extern "C" void kernel_launch(void* const* d_in, const int* in_sizes, int n_in,
                              void* d_out, int out_size)
{
    (void)in_sizes; (void)n_in; (void)out_size;
    const float* x   = (const float*)d_in[0];
    const float* Wi0 = (const float*)d_in[1];
    const float* Wh0 = (const float*)d_in[2];
    const float* Ws0 = (const float*)d_in[3];
    const float* Wi1 = (const float*)d_in[4];
    const float* Wh1 = (const float*)d_in[5];
    const float* Ws1 = (const float*)d_in[6];
    float* out = (float*)d_out;

    void* p;
    cudaGetSymbolAddress(&p, g_pre);     float* pre = (float*)p;
    cudaGetSymbolAddress(&p, g_x_hi);    __nv_bfloat16* xhi = (__nv_bfloat16*)p;
    cudaGetSymbolAddress(&p, g_x_lo);    __nv_bfloat16* xlo = (__nv_bfloat16*)p;
    cudaGetSymbolAddress(&p, g_sx1_hi);  __nv_bfloat16* sxhi = (__nv_bfloat16*)p;
    cudaGetSymbolAddress(&p, g_sx1_lo);  __nv_bfloat16* sxlo = (__nv_bfloat16*)p;
    cudaGetSymbolAddress(&p, g_hf_hi);   __nv_bfloat16* hfhi = (__nv_bfloat16*)p;
    cudaGetSymbolAddress(&p, g_hf_lo);   __nv_bfloat16* hflo = (__nv_bfloat16*)p;
    cudaGetSymbolAddress(&p, g_w0t_hi);  __nv_bfloat16* w0hi = (__nv_bfloat16*)p;
    cudaGetSymbolAddress(&p, g_w0t_lo);  __nv_bfloat16* w0lo = (__nv_bfloat16*)p;
    cudaGetSymbolAddress(&p, g_wi1t_hi); __nv_bfloat16* wi1hi = (__nv_bfloat16*)p;
    cudaGetSymbolAddress(&p, g_wi1t_lo); __nv_bfloat16* wi1lo = (__nv_bfloat16*)p;
    cudaGetSymbolAddress(&p, g_ws1t_hi); __nv_bfloat16* ws1hi = (__nv_bfloat16*)p;
    cudaGetSymbolAddress(&p, g_ws1t_lo); __nv_bfloat16* ws1lo = (__nv_bfloat16*)p;

    cudaFuncSetAttribute(recur3,
                         cudaFuncAttributeMaxDynamicSharedMemorySize, R3_BYTES);
    cudaFuncSetAttribute(tc_gemm,
                         cudaFuncAttributeMaxDynamicSharedMemorySize, GEMM_SMEM_BYTES);

    // prep: weight transpose+split, activation splits
    dim3 tb(32, 8);
    k_tsplit<<<dim3(I_DIM / 32, H_DIM / 32), tb>>>(Wi0, Ws0, w0hi, w0lo, I_DIM, H_DIM);
    k_tsplit<<<dim3(H_DIM / 32, H_DIM / 32), tb>>>(Wi1, nullptr, wi1hi, wi1lo, H_DIM, H_DIM);
    k_tsplit<<<dim3(I_DIM / 32, H_DIM / 32), tb>>>(Ws1, nullptr, ws1hi, ws1lo, I_DIM, H_DIM);
    int nx = T_DIM * B_DIM * I_DIM;
    k_xsplit<<<nx / 256, 256>>>(x, xhi, xlo, nx);
    int nsx = (T_DIM - 1) * B_DIM * I_DIM;
    k_sx1<<<(nsx + 255) / 256, 256>>>(x, sxhi, sxlo, nsx, B_DIM * I_DIM);

    // layer 0: pre0 = x @ (Wi0+Ws0)
    tc_gemm<<<dim3(H_DIM / 128, (T_DIM * B_DIM) / 128), 512, GEMM_SMEM_BYTES>>>(
        pre, xhi, xlo, I_DIM, w0hi, w0lo, nullptr, nullptr, 0, nullptr, nullptr);

    k_reset_bar<<<1, 256>>>();
    recur3<<<128, 256, R3_BYTES>>>(pre, out, Wh0, hfhi, hflo, T_DIM);

    // layer 1: pre1 = out0[1:] @ Wi1 + sx1 @ Ws1 (A0 = pre-split h series)
    tc_gemm<<<dim3(H_DIM / 128, ((T_DIM - 1) * B_DIM) / 128), 512, GEMM_SMEM_BYTES>>>(
        pre, hfhi + BH, hflo + BH, H_DIM, wi1hi, wi1lo,
        sxhi, sxlo, I_DIM, ws1hi, ws1lo);

    k_reset_bar<<<1, 256>>>();
    recur3<<<128, 256, R3_BYTES>>>(pre, out + (size_t)T_DIM * BH, Wh1, hfhi, hflo, T_DIM - 1);
}